// round 2
// baseline (speedup 1.0000x reference)
#include <cuda_runtime.h>
#include <math.h>

// ---------------- problem constants ----------------
#define BB   32
#define TT   256
#define DD   768
#define HH   512
#define H4   2048
#define NTAG 25

// ---------------- scratch (static device globals) ----------------
// xz layout: [t][b][4H]  (t*65536 + b*2048 + col)
__device__ float g_xzF[TT * BB * H4];
__device__ float g_xzB[TT * BB * H4];
// h history layout: [slot][unit][b]  (slot*16384 + u*32 + b); slot 0 = zeros (static zero-init, never written)
__device__ float g_hsF[(TT + 1) * HH * BB];
__device__ float g_hsB[(TT + 1) * HH * BB];
__device__ float g_Wt[NTAG * 1024];        // dense_w transposed [n][h]
__device__ float g_nll[BB];
// grid barrier state (epoch monotone across graph replays; cnt returns to 0)
__device__ unsigned g_bar_cnt = 0;
__device__ unsigned g_bar_epoch = 0;

// ================= Stage 1: input projection SGEMM =================
// C[(t*32+b)][n] = emb[b*256+t][k] * W[k][n] + bias[n]
// grid (16, 64, 2), block 256, tile 128x128, k-tile 8, 8x8 micro-tile
__global__ __launch_bounds__(256, 2) void gemm_kernel(
    const float* __restrict__ A,
    const float* __restrict__ Wf, const float* __restrict__ bf,
    const float* __restrict__ Wb, const float* __restrict__ bb)
{
    const float* W    = blockIdx.z ? Wb : Wf;
    const float* bias = blockIdx.z ? bb : bf;
    float*       C    = blockIdx.z ? g_xzB : g_xzF;

    __shared__ __align__(16) float As[8][128];
    __shared__ __align__(16) float Bs[8][128];

    const int t  = threadIdx.x;
    const int tx = t & 15, ty = t >> 4;
    const int m0 = blockIdx.y * 128, n0 = blockIdx.x * 128;

    const int arow = t >> 1;            // 0..127
    const int akq  = (t & 1) * 4;       // 0 or 4
    const int bk   = t >> 5;            // 0..7
    const int bn   = (t & 31) * 4;      // 0..124

    float acc[8][8];
#pragma unroll
    for (int i = 0; i < 8; i++)
#pragma unroll
        for (int j = 0; j < 8; j++) acc[i][j] = 0.f;

    for (int k0 = 0; k0 < DD; k0 += 8) {
        float4 av = *(const float4*)(A + (size_t)(m0 + arow) * DD + k0 + akq);
        As[akq + 0][arow] = av.x;
        As[akq + 1][arow] = av.y;
        As[akq + 2][arow] = av.z;
        As[akq + 3][arow] = av.w;
        float4 bv = *(const float4*)(W + (size_t)(k0 + bk) * H4 + n0 + bn);
        *(float4*)&Bs[bk][bn] = bv;
        __syncthreads();

#pragma unroll
        for (int kk = 0; kk < 8; kk++) {
            float a[8], b[8];
            *(float4*)(a)     = *(const float4*)&As[kk][ty * 4];
            *(float4*)(a + 4) = *(const float4*)&As[kk][64 + ty * 4];
            *(float4*)(b)     = *(const float4*)&Bs[kk][tx * 4];
            *(float4*)(b + 4) = *(const float4*)&Bs[kk][64 + tx * 4];
#pragma unroll
            for (int i = 0; i < 8; i++)
#pragma unroll
                for (int j = 0; j < 8; j++) acc[i][j] += a[i] * b[j];
        }
        __syncthreads();
    }

    // epilogue with bias + (b,t) -> (t,b) remap
#pragma unroll
    for (int ih = 0; ih < 2; ih++) {
#pragma unroll
        for (int i = 0; i < 4; i++) {
            int m = m0 + ih * 64 + ty * 4 + i;
            int orow = (m & 255) * 32 + (m >> 8);   // t*32 + b
            float* Crow = C + (size_t)orow * H4 + n0;
#pragma unroll
            for (int jh = 0; jh < 2; jh++) {
                int n = jh * 64 + tx * 4;
                float4 v;
                v.x = acc[ih * 4 + i][jh * 4 + 0] + bias[n0 + n + 0];
                v.y = acc[ih * 4 + i][jh * 4 + 1] + bias[n0 + n + 1];
                v.z = acc[ih * 4 + i][jh * 4 + 2] + bias[n0 + n + 2];
                v.w = acc[ih * 4 + i][jh * 4 + 3] + bias[n0 + n + 3];
                *(float4*)(Crow + n) = v;
            }
        }
    }
}

// ================= grid barrier =================
__device__ __forceinline__ void grid_barrier()
{
    __syncthreads();
    if (threadIdx.x == 0) {
        __threadfence();
        unsigned e = *((volatile unsigned*)&g_bar_epoch);
        unsigned a = atomicAdd(&g_bar_cnt, 1);
        if (a == 127u) {
            *((volatile unsigned*)&g_bar_cnt) = 0;
            __threadfence();
            atomicAdd(&g_bar_epoch, 1);
        } else {
            while (*((volatile unsigned*)&g_bar_epoch) == e) { }
        }
        __threadfence();
    }
    __syncthreads();
}

__device__ __forceinline__ float sigf(float x) { return 1.f / (1.f + expf(-x)); }

// ================= Stage 2: persistent bidirectional LSTM =================
// 128 blocks x 256 threads. Blocks 0..63: fwd, 64..127: bwd.
// Block owns units [j*8, j*8+8) => 32 z-columns {g*512 + j*8 + ul}.
// rec slice kept in registers: thread (warp kg, lane cl) holds rec[kg*64+kk][col(cl)].
__global__ __launch_bounds__(256, 1) void lstm_kernel(
    const float* __restrict__ rf, const float* __restrict__ rb)
{
    extern __shared__ float sh[];
    float* sh_h = sh;              // [512][32] = 16384 floats
    float* sh_p = sh + 16384;      // [8][32][33] = 8448 floats (padded)

    const int dir = blockIdx.x >> 6;
    const int j   = blockIdx.x & 63;
    const float* rec = dir ? rb : rf;
    const float* xz  = dir ? g_xzB : g_xzF;
    float*       hsg = dir ? g_hsB : g_hsF;

    const int t  = threadIdx.x;
    const int kg = t >> 5;                 // k-group (warp), 64 k-values each
    const int cl = t & 31;                 // column-local
    const int gate = cl >> 3, ul = cl & 7;
    const int col  = gate * 512 + j * 8 + ul;

    // load rec slice into registers (once)
    float R[64];
#pragma unroll
    for (int kk = 0; kk < 64; kk++)
        R[kk] = rec[(size_t)(kg * 64 + kk) * H4 + col];

    // gate-phase identity: u_local = warp id, b = lane
    const int gu = kg;
    const int gb = cl;
    float c = 0.f;

    for (int s = 0; s < TT; s++) {
        // stage h_prev (slot s) : straight coalesced copy ([u][b] layout)
        const float4* hsrc = (const float4*)(hsg + (size_t)s * 16384);
        float4* hdst = (float4*)sh_h;
#pragma unroll
        for (int i = 0; i < 16; i++) hdst[t + i * 256] = hsrc[t + i * 256];
        __syncthreads();

        // partial dot over this warp's 64 k-values, all 32 batches, 1 column
        float acc[32];
#pragma unroll
        for (int b = 0; b < 32; b++) acc[b] = 0.f;
        const float4* sh4 = (const float4*)(sh_h + kg * 64 * 32);
#pragma unroll 4
        for (int kk = 0; kk < 64; kk++) {
            float r = R[kk];
#pragma unroll
            for (int b4 = 0; b4 < 8; b4++) {
                float4 h4 = sh4[kk * 8 + b4];      // warp-uniform (broadcast)
                acc[b4 * 4 + 0] += r * h4.x;
                acc[b4 * 4 + 1] += r * h4.y;
                acc[b4 * 4 + 2] += r * h4.z;
                acc[b4 * 4 + 3] += r * h4.w;
            }
        }
#pragma unroll
        for (int b = 0; b < 32; b++)
            sh_p[kg * 1056 + b * 33 + cl] = acc[b];
        __syncthreads();

        // gate phase: thread (gu = unit-local, gb = batch)
        const int tn = dir ? (255 - s) : s;      // natural time for xz
        const float* xzr = xz + (size_t)tn * (BB * H4) + gb * H4 + j * 8 + gu;
        float z[4];
#pragma unroll
        for (int g = 0; g < 4; g++) {
            int cc = g * 8 + gu;
            float sm = 0.f;
#pragma unroll
            for (int q = 0; q < 8; q++) sm += sh_p[q * 1056 + gb * 33 + cc];
            z[g] = sm + xzr[g * 512];
        }
        c = sigf(z[1]) * c + sigf(z[0]) * tanhf(z[2]);
        float h = sigf(z[3]) * tanhf(c);
        hsg[(size_t)(s + 1) * 16384 + (j * 8 + gu) * 32 + gb] = h;
        __threadfence();
        grid_barrier();
    }
}

// ================= Stage 3a: transpose dense_w -> g_Wt[n][h] =================
__global__ void transpose_w(const float* __restrict__ W)
{
    int n = blockIdx.x;
    for (int u = threadIdx.x; u < 1024; u += blockDim.x)
        g_Wt[n * 1024 + u] = W[u * NTAG + n];
}

// ================= Stage 3b: dense + selu -> logits in d_out+1 =================
__global__ __launch_bounds__(256, 1) void dense_kernel(
    const float* __restrict__ db, float* __restrict__ out)
{
    extern __shared__ float sh[];
    float* shF = sh;            // [512][32]
    float* shB = sh + 16384;    // [512][32]
    const int t0 = blockIdx.x;

    const float4* srcF = (const float4*)(g_hsF + (size_t)(t0 + 1) * 16384);
    const float4* srcB = (const float4*)(g_hsB + (size_t)(TT - t0) * 16384);
    float4* dF = (float4*)shF;
    float4* dB = (float4*)shB;
    for (int i = threadIdx.x; i < 4096; i += 256) { dF[i] = srcF[i]; dB[i] = srcB[i]; }
    __syncthreads();

    const int w = threadIdx.x >> 5, lane = threadIdx.x & 31;
    if (lane < NTAG) {
        const float4* wrow = (const float4*)(g_Wt + lane * 1024);
        const float bsc = db[lane];
#pragma unroll
        for (int bb = 0; bb < 4; bb++) {
            int b = bb * 8 + w;
            float acc = bsc;
#pragma unroll 4
            for (int uq = 0; uq < 128; uq++) {
                float4 wv = wrow[uq];
                int u = uq * 4;
                acc += shF[(u + 0) * 32 + b] * wv.x + shF[(u + 1) * 32 + b] * wv.y
                     + shF[(u + 2) * 32 + b] * wv.z + shF[(u + 3) * 32 + b] * wv.w;
            }
#pragma unroll 4
            for (int uq = 0; uq < 128; uq++) {
                float4 wv = wrow[128 + uq];
                int u = uq * 4;
                acc += shB[(u + 0) * 32 + b] * wv.x + shB[(u + 1) * 32 + b] * wv.y
                     + shB[(u + 2) * 32 + b] * wv.z + shB[(u + 3) * 32 + b] * wv.w;
            }
            // selu
            float v = (acc > 0.f) ? 1.0507009873554805f * acc
                                  : 1.7580993408473768f * expm1f(acc);
            out[1 + ((size_t)b * TT + t0) * NTAG + lane] = v;
        }
    }
}

// ================= Stage 4: CRF NLL per batch =================
__global__ void crf_kernel(const int* __restrict__ targets,
                           const int* __restrict__ seq_lens,
                           const float* __restrict__ trans,
                           const float* __restrict__ out)
{
    __shared__ float tr[NTAG * NTAG];
    __shared__ float sA[NTAG];
    const int b = blockIdx.x;
    const int lane = threadIdx.x;   // 32 threads

    for (int i = lane; i < NTAG * NTAG; i += 32) tr[i] = trans[i];
    int L = seq_lens[b];
    L = min(max(L, 1), TT);
    const float* lg = out + 1 + (size_t)b * TT * NTAG;
    const int* tg = targets + b * TT;
    __syncwarp();

    // unary + binary scores (lane-parallel over t)
    float us = 0.f, bs = 0.f;
    for (int tt = lane; tt < L; tt += 32) us += lg[tt * NTAG + tg[tt]];
    for (int tt = 1 + lane; tt < L; tt += 32) bs += tr[tg[tt - 1] * NTAG + tg[tt]];
#pragma unroll
    for (int o = 16; o; o >>= 1) {
        us += __shfl_xor_sync(0xffffffffu, us, o);
        bs += __shfl_xor_sync(0xffffffffu, bs, o);
    }

    // alpha recursion
    float alpha = (lane < NTAG) ? lg[lane] : -1e30f;
    for (int tt = 1; tt < L; tt++) {
        if (lane < NTAG) sA[lane] = alpha;
        __syncwarp();
        if (lane < NTAG) {
            float m = -1e30f;
#pragma unroll
            for (int i = 0; i < NTAG; i++) m = fmaxf(m, sA[i] + tr[i * NTAG + lane]);
            float s = 0.f;
#pragma unroll
            for (int i = 0; i < NTAG; i++) s += expf(sA[i] + tr[i * NTAG + lane] - m);
            alpha = m + logf(s) + lg[tt * NTAG + lane];
        }
        __syncwarp();
    }
    // log_z = logsumexp over lanes
    float m = alpha;
#pragma unroll
    for (int o = 16; o; o >>= 1) m = fmaxf(m, __shfl_xor_sync(0xffffffffu, m, o));
    float s = (lane < NTAG) ? expf(alpha - m) : 0.f;
#pragma unroll
    for (int o = 16; o; o >>= 1) s += __shfl_xor_sync(0xffffffffu, s, o);
    float logz = m + logf(s);

    if (lane == 0) g_nll[b] = -(us + bs - logz);
}

__global__ void finalize_kernel(float* __restrict__ out)
{
    float v = g_nll[threadIdx.x];
#pragma unroll
    for (int o = 16; o; o >>= 1) v += __shfl_xor_sync(0xffffffffu, v, o);
    if (threadIdx.x == 0) out[0] = v * (1.f / 32.f);
}

// ================= launch =================
extern "C" void kernel_launch(void* const* d_in, const int* in_sizes, int n_in,
                              void* d_out, int out_size)
{
    const float* emb  = (const float*)d_in[0];
    const int*   tgt  = (const int*)d_in[1];
    const int*   slen = (const int*)d_in[2];
    const float* kf   = (const float*)d_in[3];
    const float* rf   = (const float*)d_in[4];
    const float* bf   = (const float*)d_in[5];
    const float* kb   = (const float*)d_in[6];
    const float* rb   = (const float*)d_in[7];
    const float* bb   = (const float*)d_in[8];
    const float* dw   = (const float*)d_in[9];
    const float* db   = (const float*)d_in[10];
    const float* tra  = (const float*)d_in[11];
    float* out = (float*)d_out;

    cudaFuncSetAttribute(lstm_kernel, cudaFuncAttributeMaxDynamicSharedMemorySize,
                         (16384 + 8448) * sizeof(float));
    cudaFuncSetAttribute(dense_kernel, cudaFuncAttributeMaxDynamicSharedMemorySize,
                         32768 * sizeof(float));

    gemm_kernel<<<dim3(16, 64, 2), 256>>>(emb, kf, bf, kb, bb);
    lstm_kernel<<<128, 256, (16384 + 8448) * sizeof(float)>>>(rf, rb);
    transpose_w<<<NTAG, 256>>>(dw);
    dense_kernel<<<TT, 256, 32768 * sizeof(float)>>>(db, out);
    crf_kernel<<<BB, 32>>>(tgt, slen, tra, out);
    finalize_kernel<<<1, 32>>>(out);
}

// round 8
// speedup vs baseline: 1.3029x; 1.3029x over previous
#include <cuda_runtime.h>
#include <cuda_bf16.h>
#include <stdint.h>
#include <math.h>

// ---------------- problem constants ----------------
#define BB   32
#define TT   256
#define DD   768
#define HH   512
#define H4   2048
#define NTAG 25
#define KTOT 2304      // 3 * 768 (split-bf16: Ah·Bh + Ah·Bl + Al·Bh)

typedef unsigned long long ull;
typedef unsigned int u32;

// ---------------- scratch (static device globals) ----------------
__device__ float g_xzF[TT * BB * H4];
__device__ float g_xzB[TT * BB * H4];
// h history layout: [slot][unit][b]; slot 0 = zeros (static zero-init, never written)
__device__ float g_hsF[(TT + 1) * HH * BB];
__device__ float g_hsB[(TT + 1) * HH * BB];
__device__ float g_Wt[NTAG * 1024];        // dense_w transposed [n][h]
__device__ float g_nll[BB];
// split-bf16 operands
__device__ __nv_bfloat16 g_Abf[8192 * KTOT];          // [m][ Ah | Ah | Al ]
__device__ __nv_bfloat16 g_Bbf[2 * KTOT * H4];        // per dir: [ Bh ; Bl ; Bh ][n]
// per-direction grid barrier state (epoch monotone across graph replays)
__device__ unsigned g_bar_cnt[2]   = {0, 0};
__device__ unsigned g_bar_epoch[2] = {0, 0};

// ================= Stage 0: fp32 -> split bf16 =================
__global__ void convA_kernel(const float* __restrict__ A)
{
    for (int idx = blockIdx.x * 256 + threadIdx.x; idx < 8192 * DD;
         idx += gridDim.x * 256) {
        int r = idx / DD, k = idx - r * DD;
        float x = A[idx];
        __nv_bfloat16 hi = __float2bfloat16(x);
        __nv_bfloat16 lo = __float2bfloat16(x - __bfloat162float(hi));
        __nv_bfloat16* row = g_Abf + (size_t)r * KTOT;
        row[k]        = hi;
        row[768 + k]  = hi;
        row[1536 + k] = lo;
    }
}

__global__ void convB_kernel(const float* __restrict__ Wf, const float* __restrict__ Wb)
{
    const int dir = blockIdx.y;
    const float* W = dir ? Wb : Wf;
    __nv_bfloat16* O = g_Bbf + (size_t)dir * KTOT * H4;
    for (int idx = blockIdx.x * 256 + threadIdx.x; idx < DD * H4;
         idx += gridDim.x * 256) {
        int k = idx >> 11, n = idx & 2047;
        float x = W[idx];
        __nv_bfloat16 hi = __float2bfloat16(x);
        __nv_bfloat16 lo = __float2bfloat16(x - __bfloat162float(hi));
        O[(size_t)k * H4 + n]          = hi;   // rows 0..767    : Bh
        O[(size_t)(768 + k) * H4 + n]  = lo;   // rows 768..1535 : Bl
        O[(size_t)(1536 + k) * H4 + n] = hi;   // rows 1536..2303: Bh
    }
}

// ================= Stage 1: bf16 tensor-core GEMM =================
// C[(t*32+b)][n] = A'[m][k] * B'[k][n] + bias[n],  m = b*256+t
#define CP_ASYNC16(dst, src) \
    asm volatile("cp.async.cg.shared.global [%0], [%1], 16;" :: "r"(dst), "l"(src))

__global__ __launch_bounds__(256, 2) void gemm_bf16(
    const float* __restrict__ bias_f, const float* __restrict__ bias_b)
{
    const int dir = blockIdx.z;
    const __nv_bfloat16* Ag = g_Abf;
    const __nv_bfloat16* Bg = g_Bbf + (size_t)dir * KTOT * H4;
    const float* bias = dir ? bias_b : bias_f;
    float* C = dir ? g_xzB : g_xzF;

    __shared__ __align__(16) __nv_bfloat16 As[2][128][40];
    __shared__ __align__(16) __nv_bfloat16 Bs[2][32][136];

    const int tid  = threadIdx.x;
    const int lane = tid & 31;
    const int wid  = tid >> 5;
    const int wm   = wid >> 2;
    const int wn   = wid & 3;
    const int m0   = blockIdx.y * 128, n0 = blockIdx.x * 128;

    float acc[4][4][4];
#pragma unroll
    for (int i = 0; i < 4; i++)
#pragma unroll
        for (int j = 0; j < 4; j++)
#pragma unroll
            for (int q = 0; q < 4; q++) acc[i][j][q] = 0.f;

#define LOAD_TILE(kt, buf)                                                       \
    {                                                                            \
        const int k0 = (kt) * 32;                                                \
        _Pragma("unroll")                                                        \
        for (int cc = 0; cc < 2; cc++) {                                         \
            int c = tid + cc * 256;                                              \
            int r = c >> 2, q = c & 3;                                           \
            const __nv_bfloat16* src = Ag + (size_t)(m0 + r) * KTOT + k0 + q * 8;\
            u32 dst = (u32)__cvta_generic_to_shared(&As[buf][r][q * 8]);         \
            CP_ASYNC16(dst, src);                                                \
        }                                                                        \
        _Pragma("unroll")                                                        \
        for (int cc = 0; cc < 2; cc++) {                                         \
            int c = tid + cc * 256;                                              \
            int r = c >> 4, q = c & 15;                                          \
            const __nv_bfloat16* src = Bg + (size_t)(k0 + r) * H4 + n0 + q * 8;  \
            u32 dst = (u32)__cvta_generic_to_shared(&Bs[buf][r][q * 8]);         \
            CP_ASYNC16(dst, src);                                                \
        }                                                                        \
        asm volatile("cp.async.commit_group;");                                  \
    }

    LOAD_TILE(0, 0);

    const int NKT = KTOT / 32;   // 72
    for (int kt = 0; kt < NKT; kt++) {
        const int buf = kt & 1;
        if (kt + 1 < NKT) {
            LOAD_TILE(kt + 1, buf ^ 1);
            asm volatile("cp.async.wait_group 1;");
        } else {
            asm volatile("cp.async.wait_group 0;");
        }
        __syncthreads();

#pragma unroll
        for (int ks = 0; ks < 2; ks++) {
            u32 a[4][4], b[2][4];
#pragma unroll
            for (int i = 0; i < 4; i++) {
                int row = wm * 64 + i * 16 + (lane & 15);
                int kof = ks * 16 + (lane >> 4) * 8;
                u32 sa = (u32)__cvta_generic_to_shared(&As[buf][row][kof]);
                asm volatile("ldmatrix.sync.aligned.m8n8.x4.shared.b16 {%0,%1,%2,%3}, [%4];"
                             : "=r"(a[i][0]), "=r"(a[i][1]), "=r"(a[i][2]), "=r"(a[i][3])
                             : "r"(sa));
            }
#pragma unroll
            for (int j = 0; j < 2; j++) {
                int row = ks * 16 + (lane & 15);
                int nof = wn * 32 + j * 16 + (lane >> 4) * 8;
                u32 sb = (u32)__cvta_generic_to_shared(&Bs[buf][row][nof]);
                asm volatile("ldmatrix.sync.aligned.m8n8.x4.trans.shared.b16 {%0,%1,%2,%3}, [%4];"
                             : "=r"(b[j][0]), "=r"(b[j][1]), "=r"(b[j][2]), "=r"(b[j][3])
                             : "r"(sb));
            }
#pragma unroll
            for (int i = 0; i < 4; i++)
#pragma unroll
                for (int jj = 0; jj < 4; jj++) {
                    int j = jj >> 1, s = jj & 1;
                    asm volatile(
                        "mma.sync.aligned.m16n8k16.row.col.f32.bf16.bf16.f32 "
                        "{%0,%1,%2,%3}, {%4,%5,%6,%7}, {%8,%9}, {%0,%1,%2,%3};"
                        : "+f"(acc[i][jj][0]), "+f"(acc[i][jj][1]),
                          "+f"(acc[i][jj][2]), "+f"(acc[i][jj][3])
                        : "r"(a[i][0]), "r"(a[i][1]), "r"(a[i][2]), "r"(a[i][3]),
                          "r"(b[j][s * 2]), "r"(b[j][s * 2 + 1]));
                }
        }
        __syncthreads();
    }

#pragma unroll
    for (int i = 0; i < 4; i++) {
        int mA = m0 + wm * 64 + i * 16 + (lane >> 2);
        int mB = mA + 8;
        int oA = ((mA & 255) << 5) + (mA >> 8);
        int oB = ((mB & 255) << 5) + (mB >> 8);
#pragma unroll
        for (int jj = 0; jj < 4; jj++) {
            int n = n0 + wn * 32 + jj * 8 + (lane & 3) * 2;
            float2 bv = *(const float2*)(bias + n);
            float2 v0, v1;
            v0.x = acc[i][jj][0] + bv.x;  v0.y = acc[i][jj][1] + bv.y;
            v1.x = acc[i][jj][2] + bv.x;  v1.y = acc[i][jj][3] + bv.y;
            *(float2*)(C + (size_t)oA * H4 + n) = v0;
            *(float2*)(C + (size_t)oB * H4 + n) = v1;
        }
    }
}

// ================= per-direction grid barrier (64 blocks each) =================
__device__ __forceinline__ void grid_barrier_dir(int dir)
{
    __syncthreads();
    if (threadIdx.x == 0) {
        __threadfence();
        unsigned e = *((volatile unsigned*)&g_bar_epoch[dir]);
        unsigned a = atomicAdd(&g_bar_cnt[dir], 1);
        if (a == 63u) {
            *((volatile unsigned*)&g_bar_cnt[dir]) = 0;
            __threadfence();
            atomicAdd(&g_bar_epoch[dir], 1);
        } else {
            while (*((volatile unsigned*)&g_bar_epoch[dir]) == e) { }
        }
        __threadfence();
    }
    __syncthreads();
}

__device__ __forceinline__ float sigf(float x) { return 1.f / (1.f + expf(-x)); }

// packed dual-lane fp32 FMA (Blackwell FFMA2; lane-wise IEEE fp32, bit-exact)
__device__ __forceinline__ void ffma2(ull& d, ull a, ull b)
{
    asm("fma.rn.f32x2 %0, %1, %2, %3;" : "=l"(d) : "l"(a), "l"(b), "l"(d));
}
__device__ __forceinline__ ull pack2(float x, float y)
{
    ull r;
    asm("mov.b64 %0, {%1, %2};" : "=l"(r) : "r"(__float_as_uint(x)), "r"(__float_as_uint(y)));
    return r;
}
__device__ __forceinline__ float2 unpack2(ull v)
{
    unsigned lo, hi;
    asm("mov.b64 {%0, %1}, %2;" : "=r"(lo), "=r"(hi) : "l"(v));
    return make_float2(__uint_as_float(lo), __uint_as_float(hi));
}

// ================= Stage 2: persistent bidirectional LSTM =================
// 128 blocks x 256 threads. Blocks 0..63 fwd, 64..127 bwd (independent barrier groups).
__global__ __launch_bounds__(256, 1) void lstm_kernel(
    const float* __restrict__ rf, const float* __restrict__ rb)
{
    extern __shared__ float sh[];
    float* sh_h = sh;              // [512][32]
    float* sh_p = sh + 16384;      // [8][32][33]

    const int dir = blockIdx.x >> 6;
    const int j   = blockIdx.x & 63;
    const float* rec = dir ? rb : rf;
    const float* xz  = dir ? g_xzB : g_xzF;
    float*       hsg = dir ? g_hsB : g_hsF;

    const int t  = threadIdx.x;
    const int kg = t >> 5;
    const int cl = t & 31;
    const int gate = cl >> 3, ul = cl & 7;
    const int col  = gate * 512 + j * 8 + ul;

    float R[64];
#pragma unroll
    for (int kk = 0; kk < 64; kk++)
        R[kk] = rec[(size_t)(kg * 64 + kk) * H4 + col];

    const int gu = kg;
    const int gb = cl;
    float c = 0.f;

    for (int s = 0; s < TT; s++) {
        // stage h_prev (slot s): coalesced copy ([u][b] layout)
        const float4* hsrc = (const float4*)(hsg + (size_t)s * 16384);
        float4* hdst = (float4*)sh_h;
#pragma unroll
        for (int i = 0; i < 16; i++) hdst[t + i * 256] = hsrc[t + i * 256];
        __syncthreads();

        // dot phase: packed f32x2 — acc2[i] = batches (2i, 2i+1)
        ull acc2[16];
        const ull z2 = pack2(0.f, 0.f);
#pragma unroll
        for (int i = 0; i < 16; i++) acc2[i] = z2;
        const ulonglong2* sh2 = (const ulonglong2*)(sh_h + kg * 64 * 32);
#pragma unroll 4
        for (int kk = 0; kk < 64; kk++) {
            const ull rr = pack2(R[kk], R[kk]);
#pragma unroll
            for (int b4 = 0; b4 < 8; b4++) {
                ulonglong2 h2 = sh2[kk * 8 + b4];     // warp-uniform 16B broadcast
                ffma2(acc2[b4 * 2 + 0], rr, h2.x);    // batches 4b4, 4b4+1
                ffma2(acc2[b4 * 2 + 1], rr, h2.y);    // batches 4b4+2, 4b4+3
            }
        }
#pragma unroll
        for (int i = 0; i < 16; i++) {
            float2 f = unpack2(acc2[i]);
            sh_p[kg * 1056 + (2 * i + 0) * 33 + cl] = f.x;
            sh_p[kg * 1056 + (2 * i + 1) * 33 + cl] = f.y;
        }
        __syncthreads();

        // gate phase: thread (gu = unit-local, gb = batch)
        const int tn = dir ? (255 - s) : s;
        const float* xzr = xz + (size_t)tn * (BB * H4) + gb * H4 + j * 8 + gu;
        float z[4];
#pragma unroll
        for (int g = 0; g < 4; g++) {
            int cc = g * 8 + gu;
            float sm = 0.f;
#pragma unroll
            for (int q = 0; q < 8; q++) sm += sh_p[q * 1056 + gb * 33 + cc];
            z[g] = sm + xzr[g * 512];
        }
        c = sigf(z[1]) * c + sigf(z[0]) * tanhf(z[2]);
        float h = sigf(z[3]) * tanhf(c);
        hsg[(size_t)(s + 1) * 16384 + (j * 8 + gu) * 32 + gb] = h;
        __threadfence();
        grid_barrier_dir(dir);
    }
}

// ================= Stage 3a: transpose dense_w =================
__global__ void transpose_w(const float* __restrict__ W)
{
    int n = blockIdx.x;
    for (int u = threadIdx.x; u < 1024; u += blockDim.x)
        g_Wt[n * 1024 + u] = W[u * NTAG + n];
}

// ================= Stage 3b: dense + selu =================
__global__ __launch_bounds__(256) void dense_kernel(
    const float* __restrict__ db, float* __restrict__ out)
{
    const int t0 = blockIdx.x;
    const int w = threadIdx.x >> 5, lane = threadIdx.x & 31;  // lane = batch
    const float* hF = g_hsF + (size_t)(t0 + 1) * 16384;
    const float* hB = g_hsB + (size_t)(TT - t0) * 16384;

    const int n0 = w, n1 = w + 8, n2 = w + 16, n3 = w + 24;
    float a0 = db[n0], a1 = db[n1], a2 = db[n2];
    float a3 = (n3 < NTAG) ? db[n3] : 0.f;
    const float4* W0 = (const float4*)(g_Wt + n0 * 1024);
    const float4* W1 = (const float4*)(g_Wt + n1 * 1024);
    const float4* W2 = (const float4*)(g_Wt + n2 * 1024);
    const float4* W3 = (const float4*)(g_Wt + ((n3 < NTAG) ? n3 : 0) * 1024);

#pragma unroll 4
    for (int uq = 0; uq < 128; uq++) {
        int u = uq * 4;
        float h0 = hF[(u + 0) * 32 + lane], h1 = hF[(u + 1) * 32 + lane];
        float h2 = hF[(u + 2) * 32 + lane], h3 = hF[(u + 3) * 32 + lane];
        float4 w0 = W0[uq], w1 = W1[uq], w2 = W2[uq], w3 = W3[uq];
        a0 += h0 * w0.x + h1 * w0.y + h2 * w0.z + h3 * w0.w;
        a1 += h0 * w1.x + h1 * w1.y + h2 * w1.z + h3 * w1.w;
        a2 += h0 * w2.x + h1 * w2.y + h2 * w2.z + h3 * w2.w;
        a3 += h0 * w3.x + h1 * w3.y + h2 * w3.z + h3 * w3.w;
    }
#pragma unroll 4
    for (int uq = 0; uq < 128; uq++) {
        int u = uq * 4;
        float h0 = hB[(u + 0) * 32 + lane], h1 = hB[(u + 1) * 32 + lane];
        float h2 = hB[(u + 2) * 32 + lane], h3 = hB[(u + 3) * 32 + lane];
        float4 w0 = W0[128 + uq], w1 = W1[128 + uq], w2 = W2[128 + uq], w3 = W3[128 + uq];
        a0 += h0 * w0.x + h1 * w0.y + h2 * w0.z + h3 * w0.w;
        a1 += h0 * w1.x + h1 * w1.y + h2 * w1.z + h3 * w1.w;
        a2 += h0 * w2.x + h1 * w2.y + h2 * w2.z + h3 * w2.w;
        a3 += h0 * w3.x + h1 * w3.y + h2 * w3.z + h3 * w3.w;
    }

    const float SA = 1.0507009873554805f, SB = 1.7580993408473768f;
    size_t base = 1 + ((size_t)lane * TT + t0) * NTAG;
    out[base + n0] = (a0 > 0.f) ? SA * a0 : SB * expm1f(a0);
    out[base + n1] = (a1 > 0.f) ? SA * a1 : SB * expm1f(a1);
    out[base + n2] = (a2 > 0.f) ? SA * a2 : SB * expm1f(a2);
    if (n3 < NTAG) out[base + n3] = (a3 > 0.f) ? SA * a3 : SB * expm1f(a3);
}

// ================= Stage 4: CRF NLL per batch =================
__global__ void crf_kernel(const int* __restrict__ targets,
                           const int* __restrict__ seq_lens,
                           const float* __restrict__ trans,
                           const float* __restrict__ out)
{
    __shared__ float tr[NTAG * NTAG];
    __shared__ float sA[NTAG];
    const int b = blockIdx.x;
    const int lane = threadIdx.x;

    for (int i = lane; i < NTAG * NTAG; i += 32) tr[i] = trans[i];
    int L = seq_lens[b];
    L = min(max(L, 1), TT);
    const float* lg = out + 1 + (size_t)b * TT * NTAG;
    const int* tg = targets + b * TT;
    __syncwarp();

    float us = 0.f, bs = 0.f;
    for (int tt = lane; tt < L; tt += 32) us += lg[tt * NTAG + tg[tt]];
    for (int tt = 1 + lane; tt < L; tt += 32) bs += tr[tg[tt - 1] * NTAG + tg[tt]];
#pragma unroll
    for (int o = 16; o; o >>= 1) {
        us += __shfl_xor_sync(0xffffffffu, us, o);
        bs += __shfl_xor_sync(0xffffffffu, bs, o);
    }

    float alpha = (lane < NTAG) ? lg[lane] : -1e30f;
    for (int tt = 1; tt < L; tt++) {
        if (lane < NTAG) sA[lane] = alpha;
        __syncwarp();
        if (lane < NTAG) {
            float m = -1e30f;
#pragma unroll
            for (int i = 0; i < NTAG; i++) m = fmaxf(m, sA[i] + tr[i * NTAG + lane]);
            float s = 0.f;
#pragma unroll
            for (int i = 0; i < NTAG; i++) s += expf(sA[i] + tr[i * NTAG + lane] - m);
            alpha = m + logf(s) + lg[tt * NTAG + lane];
        }
        __syncwarp();
    }
    float m = alpha;
#pragma unroll
    for (int o = 16; o; o >>= 1) m = fmaxf(m, __shfl_xor_sync(0xffffffffu, m, o));
    float s = (lane < NTAG) ? expf(alpha - m) : 0.f;
#pragma unroll
    for (int o = 16; o; o >>= 1) s += __shfl_xor_sync(0xffffffffu, s, o);
    float logz = m + logf(s);

    if (lane == 0) g_nll[b] = -(us + bs - logz);
}

__global__ void finalize_kernel(float* __restrict__ out)
{
    float v = g_nll[threadIdx.x];
#pragma unroll
    for (int o = 16; o; o >>= 1) v += __shfl_xor_sync(0xffffffffu, v, o);
    if (threadIdx.x == 0) out[0] = v * (1.f / 32.f);
}

// ================= launch =================
extern "C" void kernel_launch(void* const* d_in, const int* in_sizes, int n_in,
                              void* d_out, int out_size)
{
    const float* emb  = (const float*)d_in[0];
    const int*   tgt  = (const int*)d_in[1];
    const int*   slen = (const int*)d_in[2];
    const float* kf   = (const float*)d_in[3];
    const float* rf   = (const float*)d_in[4];
    const float* bf   = (const float*)d_in[5];
    const float* kb   = (const float*)d_in[6];
    const float* rb   = (const float*)d_in[7];
    const float* bb   = (const float*)d_in[8];
    const float* dw   = (const float*)d_in[9];
    const float* db   = (const float*)d_in[10];
    const float* tra  = (const float*)d_in[11];
    float* out = (float*)d_out;

    cudaFuncSetAttribute(lstm_kernel, cudaFuncAttributeMaxDynamicSharedMemorySize,
                         (16384 + 8448) * sizeof(float));

    convA_kernel<<<4096, 256>>>(emb);
    convB_kernel<<<dim3(2048, 2), 256>>>(kf, kb);
    gemm_bf16<<<dim3(16, 64, 2), 256>>>(bf, bb);
    lstm_kernel<<<128, 256, (16384 + 8448) * sizeof(float)>>>(rf, rb);
    transpose_w<<<NTAG, 256>>>(dw);
    dense_kernel<<<TT, 256>>>(db, out);
    crf_kernel<<<BB, 32>>>(tgt, slen, tra, out);
    finalize_kernel<<<1, 32>>>(out);
}

// round 13
// speedup vs baseline: 1.5341x; 1.1775x over previous
#include <cuda_runtime.h>
#include <cuda_bf16.h>
#include <stdint.h>
#include <math.h>

// ---------------- problem constants ----------------
#define BB   32
#define TT   256
#define DD   768
#define HH   512
#define H4   2048
#define NTAG 25
#define KTOT 2304      // 3 * 768 (split-bf16: Ah·Bh + Ah·Bl + Al·Bh)

typedef unsigned long long ull;
typedef unsigned int u32;

// ---------------- scratch (static device globals) ----------------
__device__ float g_xzF[TT * BB * H4];
__device__ float g_xzB[TT * BB * H4];
// h history layout: [slot][unit][b]; slot 0 = zeros (static zero-init, never written)
__device__ float g_hsF[(TT + 1) * HH * BB];
__device__ float g_hsB[(TT + 1) * HH * BB];
// packed split-bf16 h for the recurrence: [dir][parity][b][u], u32 = hi | lo<<16
// step 0 never reads these (stages zeros), so replay state is irrelevant.
__device__ u32 g_hbf[2][2][BB * HH];
__device__ float g_Wt[NTAG * 1024];        // dense_w transposed [n][h]
__device__ float g_nll[BB];
// split-bf16 operands for the projection GEMM
__device__ __nv_bfloat16 g_Abf[8192 * KTOT];          // [m][ Ah | Ah | Al ]
__device__ __nv_bfloat16 g_Bbf[2 * KTOT * H4];        // per dir: [ Bh ; Bl ; Bh ][n]
// per-direction grid barrier state (epoch monotone across graph replays)
__device__ unsigned g_bar_cnt[2]   = {0, 0};
__device__ unsigned g_bar_epoch[2] = {0, 0};

// ================= Stage 0: fp32 -> split bf16 =================
__global__ void convA_kernel(const float* __restrict__ A)
{
    for (int idx = blockIdx.x * 256 + threadIdx.x; idx < 8192 * DD;
         idx += gridDim.x * 256) {
        int r = idx / DD, k = idx - r * DD;
        float x = A[idx];
        __nv_bfloat16 hi = __float2bfloat16(x);
        __nv_bfloat16 lo = __float2bfloat16(x - __bfloat162float(hi));
        __nv_bfloat16* row = g_Abf + (size_t)r * KTOT;
        row[k]        = hi;
        row[768 + k]  = hi;
        row[1536 + k] = lo;
    }
}

__global__ void convB_kernel(const float* __restrict__ Wf, const float* __restrict__ Wb)
{
    const int dir = blockIdx.y;
    const float* W = dir ? Wb : Wf;
    __nv_bfloat16* O = g_Bbf + (size_t)dir * KTOT * H4;
    for (int idx = blockIdx.x * 256 + threadIdx.x; idx < DD * H4;
         idx += gridDim.x * 256) {
        int k = idx >> 11, n = idx & 2047;
        float x = W[idx];
        __nv_bfloat16 hi = __float2bfloat16(x);
        __nv_bfloat16 lo = __float2bfloat16(x - __bfloat162float(hi));
        O[(size_t)k * H4 + n]          = hi;
        O[(size_t)(768 + k) * H4 + n]  = lo;
        O[(size_t)(1536 + k) * H4 + n] = hi;
    }
}

// ================= Stage 1: bf16 tensor-core projection GEMM =================
#define CP_ASYNC16(dst, src) \
    asm volatile("cp.async.cg.shared.global [%0], [%1], 16;" :: "r"(dst), "l"(src))

__global__ __launch_bounds__(256, 2) void gemm_bf16(
    const float* __restrict__ bias_f, const float* __restrict__ bias_b)
{
    const int dir = blockIdx.z;
    const __nv_bfloat16* Ag = g_Abf;
    const __nv_bfloat16* Bg = g_Bbf + (size_t)dir * KTOT * H4;
    const float* bias = dir ? bias_b : bias_f;
    float* C = dir ? g_xzB : g_xzF;

    __shared__ __align__(16) __nv_bfloat16 As[2][128][40];
    __shared__ __align__(16) __nv_bfloat16 Bs[2][32][136];

    const int tid  = threadIdx.x;
    const int lane = tid & 31;
    const int wid  = tid >> 5;
    const int wm   = wid >> 2;
    const int wn   = wid & 3;
    const int m0   = blockIdx.y * 128, n0 = blockIdx.x * 128;

    float acc[4][4][4];
#pragma unroll
    for (int i = 0; i < 4; i++)
#pragma unroll
        for (int j = 0; j < 4; j++)
#pragma unroll
            for (int q = 0; q < 4; q++) acc[i][j][q] = 0.f;

#define LOAD_TILE(kt, buf)                                                       \
    {                                                                            \
        const int k0 = (kt) * 32;                                                \
        _Pragma("unroll")                                                        \
        for (int cc = 0; cc < 2; cc++) {                                         \
            int c = tid + cc * 256;                                              \
            int r = c >> 2, q = c & 3;                                           \
            const __nv_bfloat16* src = Ag + (size_t)(m0 + r) * KTOT + k0 + q * 8;\
            u32 dst = (u32)__cvta_generic_to_shared(&As[buf][r][q * 8]);         \
            CP_ASYNC16(dst, src);                                                \
        }                                                                        \
        _Pragma("unroll")                                                        \
        for (int cc = 0; cc < 2; cc++) {                                         \
            int c = tid + cc * 256;                                              \
            int r = c >> 4, q = c & 15;                                          \
            const __nv_bfloat16* src = Bg + (size_t)(k0 + r) * H4 + n0 + q * 8;  \
            u32 dst = (u32)__cvta_generic_to_shared(&Bs[buf][r][q * 8]);         \
            CP_ASYNC16(dst, src);                                                \
        }                                                                        \
        asm volatile("cp.async.commit_group;");                                  \
    }

    LOAD_TILE(0, 0);

    const int NKT = KTOT / 32;   // 72
    for (int kt = 0; kt < NKT; kt++) {
        const int buf = kt & 1;
        if (kt + 1 < NKT) {
            LOAD_TILE(kt + 1, buf ^ 1);
            asm volatile("cp.async.wait_group 1;");
        } else {
            asm volatile("cp.async.wait_group 0;");
        }
        __syncthreads();

#pragma unroll
        for (int ks = 0; ks < 2; ks++) {
            u32 a[4][4], b[2][4];
#pragma unroll
            for (int i = 0; i < 4; i++) {
                int row = wm * 64 + i * 16 + (lane & 15);
                int kof = ks * 16 + (lane >> 4) * 8;
                u32 sa = (u32)__cvta_generic_to_shared(&As[buf][row][kof]);
                asm volatile("ldmatrix.sync.aligned.m8n8.x4.shared.b16 {%0,%1,%2,%3}, [%4];"
                             : "=r"(a[i][0]), "=r"(a[i][1]), "=r"(a[i][2]), "=r"(a[i][3])
                             : "r"(sa));
            }
#pragma unroll
            for (int j = 0; j < 2; j++) {
                int row = ks * 16 + (lane & 15);
                int nof = wn * 32 + j * 16 + (lane >> 4) * 8;
                u32 sb = (u32)__cvta_generic_to_shared(&Bs[buf][row][nof]);
                asm volatile("ldmatrix.sync.aligned.m8n8.x4.trans.shared.b16 {%0,%1,%2,%3}, [%4];"
                             : "=r"(b[j][0]), "=r"(b[j][1]), "=r"(b[j][2]), "=r"(b[j][3])
                             : "r"(sb));
            }
#pragma unroll
            for (int i = 0; i < 4; i++)
#pragma unroll
                for (int jj = 0; jj < 4; jj++) {
                    int j = jj >> 1, s = jj & 1;
                    asm volatile(
                        "mma.sync.aligned.m16n8k16.row.col.f32.bf16.bf16.f32 "
                        "{%0,%1,%2,%3}, {%4,%5,%6,%7}, {%8,%9}, {%0,%1,%2,%3};"
                        : "+f"(acc[i][jj][0]), "+f"(acc[i][jj][1]),
                          "+f"(acc[i][jj][2]), "+f"(acc[i][jj][3])
                        : "r"(a[i][0]), "r"(a[i][1]), "r"(a[i][2]), "r"(a[i][3]),
                          "r"(b[j][s * 2]), "r"(b[j][s * 2 + 1]));
                }
        }
        __syncthreads();
    }

#pragma unroll
    for (int i = 0; i < 4; i++) {
        int mA = m0 + wm * 64 + i * 16 + (lane >> 2);
        int mB = mA + 8;
        int oA = ((mA & 255) << 5) + (mA >> 8);
        int oB = ((mB & 255) << 5) + (mB >> 8);
#pragma unroll
        for (int jj = 0; jj < 4; jj++) {
            int n = n0 + wn * 32 + jj * 8 + (lane & 3) * 2;
            float2 bv = *(const float2*)(bias + n);
            float2 v0, v1;
            v0.x = acc[i][jj][0] + bv.x;  v0.y = acc[i][jj][1] + bv.y;
            v1.x = acc[i][jj][2] + bv.x;  v1.y = acc[i][jj][3] + bv.y;
            *(float2*)(C + (size_t)oA * H4 + n) = v0;
            *(float2*)(C + (size_t)oB * H4 + n) = v1;
        }
    }
}

// ================= per-direction grid barrier (64 blocks each) =================
__device__ __forceinline__ void grid_barrier_dir(int dir)
{
    __syncthreads();
    if (threadIdx.x == 0) {
        __threadfence();
        unsigned e = *((volatile unsigned*)&g_bar_epoch[dir]);
        unsigned a = atomicAdd(&g_bar_cnt[dir], 1);
        if (a == 63u) {
            *((volatile unsigned*)&g_bar_cnt[dir]) = 0;
            __threadfence();
            atomicAdd(&g_bar_epoch[dir], 1);
        } else {
            while (*((volatile unsigned*)&g_bar_epoch[dir]) == e) { }
        }
        __threadfence();
    }
    __syncthreads();
}

__device__ __forceinline__ float sigf(float x) { return 1.f / (1.f + expf(-x)); }
__device__ __forceinline__ unsigned short bf_bits(__nv_bfloat16 h)
{
    return *reinterpret_cast<unsigned short*>(&h);
}

// ================= Stage 2: persistent bidirectional LSTM (tensor-core) ========
// 128 blocks x 256 threads. Blocks 0..63 fwd, 64..127 bwd.
// Block owns 8 units (32 z-cols). Per step: z[32b,32c] += h'[32,1536]*rec'[1536,32]
// split-bf16 segments: seg0 hh*rh, seg1 hh*rl, seg2 hl*rh.
#define SM_REC_HI 0
#define SM_REC_LO 40960
#define SM_H_HI   81920
#define SM_H_LO   115200
#define SM_ZBUF   148480
#define SM_LSTM_TOTAL (148480 + 8448 * 4)

__global__ __launch_bounds__(256, 1) void lstm_kernel(
    const float* __restrict__ rf, const float* __restrict__ rb)
{
    extern __shared__ __align__(16) char sm[];
    char*  sm_rec_hi = sm + SM_REC_HI;
    char*  sm_rec_lo = sm + SM_REC_LO;
    char*  sm_h_hi   = sm + SM_H_HI;
    char*  sm_h_lo   = sm + SM_H_LO;
    float* zbuf      = (float*)(sm + SM_ZBUF);   // [2][32][33]

    const int dir = blockIdx.x >> 6;
    const int j   = blockIdx.x & 63;
    const float* rec = dir ? rb : rf;
    const float* xz  = dir ? g_xzB : g_xzF;
    float*       hsg = dir ? g_hsB : g_hsF;

    const int t    = threadIdx.x;
    const int lane = t & 31;
    const int wid  = t >> 5;

    // ---- one-time: stage rec slice into smem as bf16 hi/lo ----
    for (int idx = t; idx < 512 * 32; idx += 256) {
        int k = idx >> 5, c = idx & 31;
        int g = c >> 3, ul = c & 7;
        float v = rec[(size_t)k * H4 + g * 512 + j * 8 + ul];
        __nv_bfloat16 hi = __float2bfloat16(v);
        __nv_bfloat16 lo = __float2bfloat16(v - __bfloat162float(hi));
        *(__nv_bfloat16*)(sm_rec_hi + k * 80 + c * 2) = hi;
        *(__nv_bfloat16*)(sm_rec_lo + k * 80 + c * 2) = lo;
    }
    __syncthreads();

    // warp-tile assignment: wm (m16), wn (n16), kh (k-half of 48 k-steps)
    const int wm = (wid >> 1) & 1;
    const int wn = wid & 1;
    const int kh = wid >> 2;
    const int arow   = wm * 16 + (lane & 15);
    const int aoff_k = (lane >> 4) * 8;
    const int brow_l = (lane & 15);
    const int bcol   = wn * 16 + (lane >> 4) * 8;

    // gate-phase identity
    const int gu = wid;          // unit-local 0..7
    const int gb = lane;         // batch
    u32* hbf_base = &g_hbf[dir][0][0];

    float c_state = 0.f;

    for (int s = 0; s < TT; s++) {
        // prefetch xz for gate phase
        const int tn = dir ? (255 - s) : s;
        const float* xzr = xz + (size_t)tn * (BB * H4) + gb * H4 + j * 8 + gu;
        float xpre[4];
#pragma unroll
        for (int g = 0; g < 4; g++) xpre[g] = xzr[g * 512];

        // ---- stage h' (packed u32 -> smem bf16 hi/lo, [b][u] layout) ----
        const u32* src = hbf_base + (s & 1) * (BB * HH);
#pragma unroll 4
        for (int i = 0; i < 16; i++) {
            int idx4 = t + i * 256;          // 0..4095
            int b  = idx4 >> 7;
            int u0 = (idx4 & 127) * 4;
            uint4 p;
            if (s == 0) { p.x = p.y = p.z = p.w = 0u; }
            else        { p = ((const uint4*)src)[idx4]; }
            u32 hi0 = __byte_perm(p.x, p.y, 0x5410);
            u32 lo0 = __byte_perm(p.x, p.y, 0x7632);
            u32 hi1 = __byte_perm(p.z, p.w, 0x5410);
            u32 lo1 = __byte_perm(p.z, p.w, 0x7632);
            *(uint2*)(sm_h_hi + b * 1040 + u0 * 2) = make_uint2(hi0, hi1);
            *(uint2*)(sm_h_lo + b * 1040 + u0 * 2) = make_uint2(lo0, lo1);
        }
        __syncthreads();

        // ---- mma phase: 48 k-steps for this k-half ----
        float acc[2][4];
#pragma unroll
        for (int jj = 0; jj < 2; jj++)
#pragma unroll
            for (int q = 0; q < 4; q++) acc[jj][q] = 0.f;

        const int ks0 = kh * 48;
#pragma unroll 4
        for (int ks = ks0; ks < ks0 + 48; ks++) {
            int seg = ks >> 5, kk = ks & 31;
            const char* Ab = (seg < 2)  ? sm_h_hi   : sm_h_lo;
            const char* Bb = (seg == 1) ? sm_rec_lo : sm_rec_hi;
            u32 a[4], b[4];
            u32 sa = (u32)__cvta_generic_to_shared(Ab + arow * 1040 + (kk * 16 + aoff_k) * 2);
            asm volatile("ldmatrix.sync.aligned.m8n8.x4.shared.b16 {%0,%1,%2,%3}, [%4];"
                         : "=r"(a[0]), "=r"(a[1]), "=r"(a[2]), "=r"(a[3]) : "r"(sa));
            u32 sb = (u32)__cvta_generic_to_shared(Bb + (kk * 16 + brow_l) * 80 + bcol * 2);
            asm volatile("ldmatrix.sync.aligned.m8n8.x4.trans.shared.b16 {%0,%1,%2,%3}, [%4];"
                         : "=r"(b[0]), "=r"(b[1]), "=r"(b[2]), "=r"(b[3]) : "r"(sb));
#pragma unroll
            for (int jj = 0; jj < 2; jj++) {
                asm volatile(
                    "mma.sync.aligned.m16n8k16.row.col.f32.bf16.bf16.f32 "
                    "{%0,%1,%2,%3}, {%4,%5,%6,%7}, {%8,%9}, {%0,%1,%2,%3};"
                    : "+f"(acc[jj][0]), "+f"(acc[jj][1]),
                      "+f"(acc[jj][2]), "+f"(acc[jj][3])
                    : "r"(a[0]), "r"(a[1]), "r"(a[2]), "r"(a[3]),
                      "r"(b[jj * 2]), "r"(b[jj * 2 + 1]));
            }
        }

        // ---- store z partials ----
        {
            float* zh = zbuf + kh * (32 * 33);
            int r0 = wm * 16 + (lane >> 2);
#pragma unroll
            for (int jj = 0; jj < 2; jj++) {
                int cc = wn * 16 + jj * 8 + (lane & 3) * 2;
                zh[r0 * 33 + cc]           = acc[jj][0];
                zh[r0 * 33 + cc + 1]       = acc[jj][1];
                zh[(r0 + 8) * 33 + cc]     = acc[jj][2];
                zh[(r0 + 8) * 33 + cc + 1] = acc[jj][3];
            }
        }
        __syncthreads();

        // ---- gate phase ----
        float z[4];
#pragma unroll
        for (int g = 0; g < 4; g++) {
            int cc = g * 8 + gu;
            z[g] = zbuf[gb * 33 + cc] + zbuf[32 * 33 + gb * 33 + cc] + xpre[g];
        }
        c_state = sigf(z[1]) * c_state + sigf(z[0]) * tanhf(z[2]);
        float h = sigf(z[3]) * tanhf(c_state);

        // fp32 history for dense
        hsg[(size_t)(s + 1) * 16384 + (j * 8 + gu) * 32 + gb] = h;
        // packed split-bf16 for next step
        {
            __nv_bfloat16 hi = __float2bfloat16(h);
            __nv_bfloat16 lo = __float2bfloat16(h - __bfloat162float(hi));
            u32 packed = (u32)bf_bits(hi) | ((u32)bf_bits(lo) << 16);
            hbf_base[((s + 1) & 1) * (BB * HH) + gb * HH + j * 8 + gu] = packed;
        }
        __threadfence();
        grid_barrier_dir(dir);
    }
}

// ================= Stage 3a: transpose dense_w =================
__global__ void transpose_w(const float* __restrict__ W)
{
    int n = blockIdx.x;
    for (int u = threadIdx.x; u < 1024; u += blockDim.x)
        g_Wt[n * 1024 + u] = W[u * NTAG + n];
}

// ================= Stage 3b: dense + selu =================
__global__ __launch_bounds__(256) void dense_kernel(
    const float* __restrict__ db, float* __restrict__ out)
{
    const int t0 = blockIdx.x;
    const int w = threadIdx.x >> 5, lane = threadIdx.x & 31;  // lane = batch
    const float* hF = g_hsF + (size_t)(t0 + 1) * 16384;
    const float* hB = g_hsB + (size_t)(TT - t0) * 16384;

    const int n0 = w, n1 = w + 8, n2 = w + 16, n3 = w + 24;
    float a0 = db[n0], a1 = db[n1], a2 = db[n2];
    float a3 = (n3 < NTAG) ? db[n3] : 0.f;
    const float4* W0 = (const float4*)(g_Wt + n0 * 1024);
    const float4* W1 = (const float4*)(g_Wt + n1 * 1024);
    const float4* W2 = (const float4*)(g_Wt + n2 * 1024);
    const float4* W3 = (const float4*)(g_Wt + ((n3 < NTAG) ? n3 : 0) * 1024);

#pragma unroll 4
    for (int uq = 0; uq < 128; uq++) {
        int u = uq * 4;
        float h0 = hF[(u + 0) * 32 + lane], h1 = hF[(u + 1) * 32 + lane];
        float h2 = hF[(u + 2) * 32 + lane], h3 = hF[(u + 3) * 32 + lane];
        float4 w0 = W0[uq], w1 = W1[uq], w2 = W2[uq], w3 = W3[uq];
        a0 += h0 * w0.x + h1 * w0.y + h2 * w0.z + h3 * w0.w;
        a1 += h0 * w1.x + h1 * w1.y + h2 * w1.z + h3 * w1.w;
        a2 += h0 * w2.x + h1 * w2.y + h2 * w2.z + h3 * w2.w;
        a3 += h0 * w3.x + h1 * w3.y + h2 * w3.z + h3 * w3.w;
    }
#pragma unroll 4
    for (int uq = 0; uq < 128; uq++) {
        int u = uq * 4;
        float h0 = hB[(u + 0) * 32 + lane], h1 = hB[(u + 1) * 32 + lane];
        float h2 = hB[(u + 2) * 32 + lane], h3 = hB[(u + 3) * 32 + lane];
        float4 w0 = W0[128 + uq], w1 = W1[128 + uq], w2 = W2[128 + uq], w3 = W3[128 + uq];
        a0 += h0 * w0.x + h1 * w0.y + h2 * w0.z + h3 * w0.w;
        a1 += h0 * w1.x + h1 * w1.y + h2 * w1.z + h3 * w1.w;
        a2 += h0 * w2.x + h1 * w2.y + h2 * w2.z + h3 * w2.w;
        a3 += h0 * w3.x + h1 * w3.y + h2 * w3.z + h3 * w3.w;
    }

    const float SA = 1.0507009873554805f, SB = 1.7580993408473768f;
    size_t base = 1 + ((size_t)lane * TT + t0) * NTAG;
    out[base + n0] = (a0 > 0.f) ? SA * a0 : SB * expm1f(a0);
    out[base + n1] = (a1 > 0.f) ? SA * a1 : SB * expm1f(a1);
    out[base + n2] = (a2 > 0.f) ? SA * a2 : SB * expm1f(a2);
    if (n3 < NTAG) out[base + n3] = (a3 > 0.f) ? SA * a3 : SB * expm1f(a3);
}

// ================= Stage 4: CRF NLL per batch =================
__global__ void crf_kernel(const int* __restrict__ targets,
                           const int* __restrict__ seq_lens,
                           const float* __restrict__ trans,
                           const float* __restrict__ out)
{
    __shared__ float tr[NTAG * NTAG];
    __shared__ float sA[NTAG];
    const int b = blockIdx.x;
    const int lane = threadIdx.x;

    for (int i = lane; i < NTAG * NTAG; i += 32) tr[i] = trans[i];
    int L = seq_lens[b];
    L = min(max(L, 1), TT);
    const float* lg = out + 1 + (size_t)b * TT * NTAG;
    const int* tg = targets + b * TT;
    __syncwarp();

    float us = 0.f, bs = 0.f;
    for (int tt = lane; tt < L; tt += 32) us += lg[tt * NTAG + tg[tt]];
    for (int tt = 1 + lane; tt < L; tt += 32) bs += tr[tg[tt - 1] * NTAG + tg[tt]];
#pragma unroll
    for (int o = 16; o; o >>= 1) {
        us += __shfl_xor_sync(0xffffffffu, us, o);
        bs += __shfl_xor_sync(0xffffffffu, bs, o);
    }

    float alpha = (lane < NTAG) ? lg[lane] : -1e30f;
    for (int tt = 1; tt < L; tt++) {
        if (lane < NTAG) sA[lane] = alpha;
        __syncwarp();
        if (lane < NTAG) {
            float m = -1e30f;
#pragma unroll
            for (int i = 0; i < NTAG; i++) m = fmaxf(m, sA[i] + tr[i * NTAG + lane]);
            float s = 0.f;
#pragma unroll
            for (int i = 0; i < NTAG; i++) s += expf(sA[i] + tr[i * NTAG + lane] - m);
            alpha = m + logf(s) + lg[tt * NTAG + lane];
        }
        __syncwarp();
    }
    float m = alpha;
#pragma unroll
    for (int o = 16; o; o >>= 1) m = fmaxf(m, __shfl_xor_sync(0xffffffffu, m, o));
    float s = (lane < NTAG) ? expf(alpha - m) : 0.f;
#pragma unroll
    for (int o = 16; o; o >>= 1) s += __shfl_xor_sync(0xffffffffu, s, o);
    float logz = m + logf(s);

    if (lane == 0) g_nll[b] = -(us + bs - logz);
}

__global__ void finalize_kernel(float* __restrict__ out)
{
    float v = g_nll[threadIdx.x];
#pragma unroll
    for (int o = 16; o; o >>= 1) v += __shfl_xor_sync(0xffffffffu, v, o);
    if (threadIdx.x == 0) out[0] = v * (1.f / 32.f);
}

// ================= launch =================
extern "C" void kernel_launch(void* const* d_in, const int* in_sizes, int n_in,
                              void* d_out, int out_size)
{
    const float* emb  = (const float*)d_in[0];
    const int*   tgt  = (const int*)d_in[1];
    const int*   slen = (const int*)d_in[2];
    const float* kf   = (const float*)d_in[3];
    const float* rf   = (const float*)d_in[4];
    const float* bf   = (const float*)d_in[5];
    const float* kb   = (const float*)d_in[6];
    const float* rb   = (const float*)d_in[7];
    const float* bb   = (const float*)d_in[8];
    const float* dw   = (const float*)d_in[9];
    const float* db   = (const float*)d_in[10];
    const float* tra  = (const float*)d_in[11];
    float* out = (float*)d_out;

    cudaFuncSetAttribute(lstm_kernel, cudaFuncAttributeMaxDynamicSharedMemorySize,
                         SM_LSTM_TOTAL);

    convA_kernel<<<4096, 256>>>(emb);
    convB_kernel<<<dim3(2048, 2), 256>>>(kf, kb);
    gemm_bf16<<<dim3(16, 64, 2), 256>>>(bf, bb);
    lstm_kernel<<<128, 256, SM_LSTM_TOTAL>>>(rf, rb);
    transpose_w<<<NTAG, 256>>>(dw);
    dense_kernel<<<TT, 256>>>(db, out);
    crf_kernel<<<BB, 32>>>(tgt, slen, tra, out);
    finalize_kernel<<<1, 32>>>(out);
}